// round 1
// baseline (speedup 1.0000x reference)
#include <cuda_runtime.h>
#include <math.h>
#include <stdint.h>

// ---------------------------------------------------------------------------
// ProjectionDecoder fused kernel.
// Pipeline per sample n (2048): Wigner-D rotate (49x10 complex) ->
// signal 10x14x14 -> bilinear proj 10x64x64 -> convT 4x4 s2 p1 -> 1x128x128.
// ---------------------------------------------------------------------------

#define NDEG 6
#define MTOT 49          // (NDEG+1)^2
#define REP 10
#define JGRID 14         // 2B
#define PROJ 64
#define OUTW 128

__constant__ float c_FACT[13] = {
    1.f, 1.f, 2.f, 6.f, 24.f, 120.f, 720.f, 5040.f, 40320.f,
    362880.f, 3628800.f, 39916800.f, 479001600.f};
__constant__ int c_OFF[8] = {0, 1, 10, 35, 84, 165, 286, 455};

// Precomputed (input-independent) tables, rebuilt every launch by prep kernel.
__device__ float g_Yre[MTOT * 196];
__device__ float g_Yim[MTOT * 196];
__device__ int   g_boff[4 * 4096];
__device__ float g_bw[4 * 4096];

// ---------------------------------------------------------------------------
// Prep kernel: spherical-harmonic tables + bilinear sampling tables.
// ---------------------------------------------------------------------------
__global__ void prep_kernel() {
    const int tid = threadIdx.x;
    const double PI = 3.14159265358979323846;

    // ---- Y tables: one thread per beta index jb (14 of them) ----
    if (tid < JGRID) {
        int jb = tid;
        double beta = PI * (2.0 * jb + 1.0) / 28.0;   // pi*(2j+1)/(4B), B=7
        double x = cos(beta), sx = sin(beta);
        double P[NDEG + 1][NDEG + 1];
        for (int a = 0; a <= NDEG; ++a)
            for (int b = 0; b <= NDEG; ++b) P[a][b] = 0.0;
        P[0][0] = 1.0;
        for (int m = 1; m <= NDEG; ++m)
            P[m][m] = -(2.0 * m - 1.0) * sx * P[m - 1][m - 1];
        for (int m = 0; m <= NDEG; ++m) {
            if (m + 1 <= NDEG) P[m + 1][m] = (2.0 * m + 1.0) * x * P[m][m];
            for (int l = m + 2; l <= NDEG; ++l)
                P[l][m] = ((2.0 * l - 1.0) * x * P[l - 1][m] -
                           (l + m - 1.0) * P[l - 2][m]) / (double)(l - m);
        }
        double dfact[13];
        dfact[0] = 1.0;
        for (int q = 1; q <= 12; ++q) dfact[q] = dfact[q - 1] * q;
        for (int l = 0; l <= NDEG; ++l) {
            for (int m = 0; m <= l; ++m) {
                double Nrm = sqrt((2.0 * l + 1.0) / (4.0 * PI) *
                                  dfact[l - m] / dfact[l + m]);
                double pr = Nrm * P[l][m];
                for (int k = 0; k < JGRID; ++k) {
                    double alpha = 2.0 * PI * k / 14.0;
                    double yre = pr * cos(m * alpha);
                    double yim = pr * sin(m * alpha);
                    int col = jb * JGRID + k;
                    g_Yre[(l * l + l + m) * 196 + col] = (float)yre;
                    g_Yim[(l * l + l + m) * 196 + col] = (float)yim;
                    if (m > 0) {
                        double sgn = (m & 1) ? -1.0 : 1.0;
                        g_Yre[(l * l + l - m) * 196 + col] = (float)(sgn * yre);
                        g_Yim[(l * l + l - m) * 196 + col] = (float)(-sgn * yim);
                    }
                }
            }
        }
    }

    // ---- bilinear tap table for the orthographic grid ----
    for (int p = tid; p < 4096; p += blockDim.x) {
        int py = p >> 6, px = p & 63;
        double r = 0.8;
        double yv = -r + px * 0.0;  // placeholder (overwritten below)
        yv = -r + py * (2.0 * r / 63.0);
        double xv = -r + px * (2.0 * r / 63.0);
        double rho = sqrt(xv * xv + yv * yv);
        double rc = rho < 1.0 ? rho : 1.0;
        double th = asin(rc);
        double ph = atan2(yv, xv);
        float gx = (float)(ph / PI);
        float gy = (float)(2.0 * th / PI - 1.0);
        float gxp = (gx + 1.0f) * 14.0f / 2.0f - 0.5f;
        float gyp = (gy + 1.0f) * 14.0f / 2.0f - 0.5f;
        float x0f = floorf(gxp), y0f = floorf(gyp);
        float wx1 = gxp - x0f, wx0 = 1.0f - wx1;
        float wy1 = gyp - y0f, wy0 = 1.0f - wy1;
        int xi0 = (int)x0f, yi0 = (int)y0f;
        int xs[4] = {xi0, xi0 + 1, xi0, xi0 + 1};
        int ys[4] = {yi0, yi0, yi0 + 1, yi0 + 1};
        float ws[4] = {wx0 * wy0, wx1 * wy0, wx0 * wy1, wx1 * wy1};
        for (int t = 0; t < 4; ++t) {
            bool valid = (xs[t] >= 0) && (xs[t] < 14) && (ys[t] >= 0) && (ys[t] < 14);
            int xc = xs[t] < 0 ? 0 : (xs[t] > 13 ? 13 : xs[t]);
            int yc = ys[t] < 0 ? 0 : (ys[t] > 13 ? 13 : ys[t]);
            g_boff[t * 4096 + p] = yc * 14 + xc;
            g_bw[t * 4096 + p] = valid ? ws[t] : 0.0f;
        }
    }
}

// ---------------------------------------------------------------------------
// Main fused kernel: one CTA per sample.
// smem layout (floats):
//  [0..79]      trig (cA@0, sA@16, cG@32, sG@48, cb@64, sb@65)
//  [80..239]    wt (10*16)
//  [240..695]   wigner d (455)
//  [696..1283]  Sre (49*12)
//  [1284..1871] Sim (49*12)
//  [1872..4223] sig (196*12)  (aliased as staged spectrum in phase 2)
//  [4224..48443] proj (10 * 66 * 67), zero-padded borders
// ---------------------------------------------------------------------------
#define SM_TRIG 0
#define SM_WT   80
#define SM_D    240
#define SM_SRE  696
#define SM_SIM  1284
#define SM_SIG  1872
#define SM_PROJ 4224
#define SM_TOTAL_FLOATS 48444
#define PROJ_PITCH 67
#define PROJ_CH (66 * 67)

__global__ __launch_bounds__(512, 1)
void decoder_kernel(const float* __restrict__ angles,
                    const float* __restrict__ spectrum,
                    const float* __restrict__ wt,
                    const float* __restrict__ bt,
                    float* __restrict__ out) {
    extern __shared__ float sm[];
    const int tid = threadIdx.x;
    const int n = blockIdx.x;

    float* s_trig = sm + SM_TRIG;
    float* s_wt   = sm + SM_WT;
    float* s_d    = sm + SM_D;
    float* s_Sre  = sm + SM_SRE;
    float* s_Sim  = sm + SM_SIM;
    float* s_sig  = sm + SM_SIG;
    float* s_proj = sm + SM_PROJ;
    float* s_spec = s_sig;  // alias: staged spectrum, dead before sig written

    // ---- phase 0: trig tables + staging ----
    if (tid < 13) {
        float al = angles[3 * n + 0];
        float ga = angles[3 * n + 2];
        float kk = (float)(tid - 6);
        float s, c;
        sincosf(kk * al, &s, &c); s_trig[16 + tid] = s; s_trig[0 + tid] = c;
        sincosf(kk * ga, &s, &c); s_trig[48 + tid] = s; s_trig[32 + tid] = c;
    }
    if (tid == 16) {
        float be = angles[3 * n + 1];
        float s, c;
        sincosf(0.5f * be, &s, &c);
        s_trig[64] = c; s_trig[65] = s;
    }
    for (int i = tid; i < 160; i += 512) s_wt[i] = wt[i];
    for (int i = tid; i < 980; i += 512) s_spec[i] = spectrum[i];
    __syncthreads();

    // ---- phase 1: Wigner small-d entries (455) ----
    {
        const float cb = s_trig[64], sb = s_trig[65];
        for (int e = tid; e < 455; e += 512) {
            int l = 0;
            while (l < 6 && e >= c_OFF[l + 1]) ++l;
            int r = e - c_OFF[l];
            int n1 = 2 * l + 1;
            int i = r / n1, j = r - i * n1;
            int mp = i - l, m = j - l;
            float pref = sqrtf(c_FACT[l + mp] * c_FACT[l - mp] *
                               c_FACT[l + m] * c_FACT[l - m]);
            int kmin = m - mp > 0 ? m - mp : 0;
            int kmax = (l + m) < (l - mp) ? (l + m) : (l - mp);
            float acc = 0.f;
            for (int k = kmin; k <= kmax; ++k) {
                float cc = pref / (c_FACT[l + m - k] * c_FACT[k] *
                                   c_FACT[l - mp - k] * c_FACT[mp - m + k]);
                if ((mp - m + k) & 1) cc = -cc;
                int pc = 2 * l + m - mp - 2 * k;
                int ps = mp - m + 2 * k;
                float pcv = 1.f;
                for (int q = 0; q < pc; ++q) pcv *= cb;
                float psv = 1.f;
                for (int q = 0; q < ps; ++q) psv *= sb;
                acc += cc * pcv * psv;
            }
            s_d[e] = acc;
        }
    }
    __syncthreads();

    // ---- phase 2: rotate spectrum -> Sre/Sim (49 x 10), pitch 12 ----
    for (int idx = tid; idx < 490; idx += 512) {
        int mrow = idx / 10, c = idx - mrow * 10;
        int l = 0;
        while ((l + 1) * (l + 1) <= mrow) ++l;
        int i = mrow - l * l;
        int mp = i - l;
        float camp = s_trig[0 + mp + 6], samp = s_trig[16 + mp + 6];
        const float* dptr = s_d + c_OFF[l] + i * (2 * l + 1);
        float are = 0.f, aim = 0.f;
        for (int j = 0; j <= 2 * l; ++j) {
            int m = j - l;
            float dv = dptr[j];
            float cg = s_trig[32 + m + 6], sg = s_trig[48 + m + 6];
            float cosang = camp * cg - samp * sg;
            float sinang = samp * cg + camp * sg;
            float sre = s_spec[(l * l + j) * 20 + c * 2 + 0];
            float sim = s_spec[(l * l + j) * 20 + c * 2 + 1];
            are += dv * (cosang * sre + sinang * sim);
            aim += dv * (cosang * sim - sinang * sre);
        }
        s_Sre[mrow * 12 + c] = are;
        s_Sim[mrow * 12 + c] = aim;
    }
    __syncthreads();

    // ---- phase 3: signal[j][c] = sum_m Sre[m][c]*Yre[m][j] - Sim*Yim ----
    if (tid < 196) {
        float acc[10];
#pragma unroll
        for (int c = 0; c < 10; ++c) acc[c] = 0.f;
#pragma unroll 7
        for (int m = 0; m < 49; ++m) {
            float yre = g_Yre[m * 196 + tid];
            float yim = g_Yim[m * 196 + tid];
            float4 r0 = *(const float4*)&s_Sre[m * 12 + 0];
            float4 r1 = *(const float4*)&s_Sre[m * 12 + 4];
            float2 r2 = *(const float2*)&s_Sre[m * 12 + 8];
            float4 i0 = *(const float4*)&s_Sim[m * 12 + 0];
            float4 i1 = *(const float4*)&s_Sim[m * 12 + 4];
            float2 i2 = *(const float2*)&s_Sim[m * 12 + 8];
            acc[0] += r0.x * yre - i0.x * yim;
            acc[1] += r0.y * yre - i0.y * yim;
            acc[2] += r0.z * yre - i0.z * yim;
            acc[3] += r0.w * yre - i0.w * yim;
            acc[4] += r1.x * yre - i1.x * yim;
            acc[5] += r1.y * yre - i1.y * yim;
            acc[6] += r1.z * yre - i1.z * yim;
            acc[7] += r1.w * yre - i1.w * yim;
            acc[8] += r2.x * yre - i2.x * yim;
            acc[9] += r2.y * yre - i2.y * yim;
        }
        float4 w0 = make_float4(acc[0], acc[1], acc[2], acc[3]);
        float4 w1 = make_float4(acc[4], acc[5], acc[6], acc[7]);
        float2 w2 = make_float2(acc[8], acc[9]);
        *(float4*)&s_sig[tid * 12 + 0] = w0;
        *(float4*)&s_sig[tid * 12 + 4] = w1;
        *(float2*)&s_sig[tid * 12 + 8] = w2;
    }
    __syncthreads();

    // ---- phase 4: projection (bilinear) into padded smem ----
    for (int i = tid; i < 670; i += 512) {
        int c = i / 67, q = i - c * 67;
        s_proj[c * PROJ_CH + q] = 0.f;
        s_proj[c * PROJ_CH + 65 * PROJ_PITCH + q] = 0.f;
    }
    for (int i = tid; i < 640; i += 512) {
        int c = i / 64, rr = i - c * 64;
        s_proj[c * PROJ_CH + (rr + 1) * PROJ_PITCH + 0] = 0.f;
        s_proj[c * PROJ_CH + (rr + 1) * PROJ_PITCH + 65] = 0.f;
    }
    for (int p = tid; p < 4096; p += 512) {
        int py = p >> 6, px = p & 63;
        float tv[4][10];
        float w[4];
#pragma unroll
        for (int t = 0; t < 4; ++t) {
            int off = g_boff[t * 4096 + p];
            w[t] = g_bw[t * 4096 + p];
            const float* sp = &s_sig[off * 12];
            float4 q0 = *(const float4*)(sp + 0);
            float4 q1 = *(const float4*)(sp + 4);
            float2 q2 = *(const float2*)(sp + 8);
            tv[t][0] = q0.x; tv[t][1] = q0.y; tv[t][2] = q0.z; tv[t][3] = q0.w;
            tv[t][4] = q1.x; tv[t][5] = q1.y; tv[t][6] = q1.z; tv[t][7] = q1.w;
            tv[t][8] = q2.x; tv[t][9] = q2.y;
        }
        float* pdst = &s_proj[(py + 1) * PROJ_PITCH + (px + 1)];
#pragma unroll
        for (int c = 0; c < 10; ++c) {
            float v = w[0] * tv[0][c] + w[1] * tv[1][c] +
                      w[2] * tv[2][c] + w[3] * tv[3][c];
            pdst[c * PROJ_CH] = v;
        }
    }
    __syncthreads();

    // ---- phase 5: ConvTranspose2d, 4x8 output tile per thread ----
    {
        const int b = tid & 15;      // col block (8 cols)
        const int a = tid >> 4;      // row block (4 rows)
        const float bias = bt[0];
        float acc[4][8];
#pragma unroll
        for (int dy = 0; dy < 4; ++dy)
#pragma unroll
            for (int e = 0; e < 8; ++e) acc[dy][e] = bias;

        const int rowbase = 2 * a;   // padded proj row of iy = 2a-1
        const int colbase = 4 * b;   // padded proj col of ix = 4b-1

        // row mapping per dy: (r1,kh1) + (r2,kh2)
        const int R1[4] = {1, 2, 2, 3};
        const int KH1[4] = {1, 0, 1, 0};
        const int R2[4] = {0, 1, 1, 2};
        const int KH2[4] = {3, 2, 3, 2};
        // col mapping per e: (c1,kw1) + (c2,kw2)
        const int C1[8] = {1, 2, 2, 3, 3, 4, 4, 5};
        const int KW1[8] = {1, 0, 1, 0, 1, 0, 1, 0};
        const int C2[8] = {0, 1, 1, 2, 2, 3, 3, 4};
        const int KW2[8] = {3, 2, 3, 2, 3, 2, 3, 2};

#pragma unroll 1
        for (int c = 0; c < 10; ++c) {
            float w[16];
            const float* pw = s_wt + c * 16;
            float4 w0 = *(const float4*)(pw + 0);
            float4 w1 = *(const float4*)(pw + 4);
            float4 w2 = *(const float4*)(pw + 8);
            float4 w3 = *(const float4*)(pw + 12);
            w[0] = w0.x; w[1] = w0.y; w[2] = w0.z; w[3] = w0.w;
            w[4] = w1.x; w[5] = w1.y; w[6] = w1.z; w[7] = w1.w;
            w[8] = w2.x; w[9] = w2.y; w[10] = w2.z; w[11] = w2.w;
            w[12] = w3.x; w[13] = w3.y; w[14] = w3.z; w[15] = w3.w;

            float pv[4][6];
            const float* pp = s_proj + c * PROJ_CH + rowbase * PROJ_PITCH + colbase;
#pragma unroll
            for (int r = 0; r < 4; ++r)
#pragma unroll
                for (int q = 0; q < 6; ++q) pv[r][q] = pp[r * PROJ_PITCH + q];

#pragma unroll
            for (int dy = 0; dy < 4; ++dy) {
                const int r1 = R1[dy], r2 = R2[dy];
                const int h1 = KH1[dy] * 4, h2 = KH2[dy] * 4;
#pragma unroll
                for (int e = 0; e < 8; ++e) {
                    acc[dy][e] += pv[r1][C1[e]] * w[h1 + KW1[e]];
                    acc[dy][e] += pv[r1][C2[e]] * w[h1 + KW2[e]];
                    acc[dy][e] += pv[r2][C1[e]] * w[h2 + KW1[e]];
                    acc[dy][e] += pv[r2][C2[e]] * w[h2 + KW2[e]];
                }
            }
        }

        float* op = out + (size_t)n * 16384 + (size_t)(4 * a) * 128 + 8 * b;
#pragma unroll
        for (int dy = 0; dy < 4; ++dy) {
            *(float4*)(op + dy * 128 + 0) =
                make_float4(acc[dy][0], acc[dy][1], acc[dy][2], acc[dy][3]);
            *(float4*)(op + dy * 128 + 4) =
                make_float4(acc[dy][4], acc[dy][5], acc[dy][6], acc[dy][7]);
        }
    }
}

// ---------------------------------------------------------------------------
extern "C" void kernel_launch(void* const* d_in, const int* in_sizes, int n_in,
                              void* d_out, int out_size) {
    const float* angles   = (const float*)d_in[0];
    const float* spectrum = (const float*)d_in[1];
    const float* wt       = (const float*)d_in[2];
    const float* bt       = (const float*)d_in[3];
    float* out = (float*)d_out;
    (void)in_sizes; (void)n_in; (void)out_size;

    const size_t smem_bytes = SM_TOTAL_FLOATS * sizeof(float);
    cudaFuncSetAttribute(decoder_kernel,
                         cudaFuncAttributeMaxDynamicSharedMemorySize,
                         (int)smem_bytes);

    prep_kernel<<<1, 256>>>();
    decoder_kernel<<<2048, 512, smem_bytes>>>(angles, spectrum, wt, bt, out);
}

// round 4
// speedup vs baseline: 5.2880x; 5.2880x over previous
#include <cuda_runtime.h>
#include <cuda_fp16.h>
#include <math.h>
#include <stdint.h>

// ---------------------------------------------------------------------------
// ProjectionDecoder fused kernel.
// Pipeline per sample n (2048): Wigner-D rotate (49x10 complex) ->
// signal 10x14x14 -> bilinear proj 10x64x64 (fp16 smem) -> convT 4x4 s2 p1
// -> 1x128x128 fp32.
// ---------------------------------------------------------------------------

#define NDEG 6
#define MTOT 49
#define JGRID 14

__constant__ float c_FACT[13] = {
    1.f, 1.f, 2.f, 6.f, 24.f, 120.f, 720.f, 5040.f, 40320.f,
    362880.f, 3628800.f, 39916800.f, 479001600.f};
__constant__ int c_OFF[8] = {0, 1, 10, 35, 84, 165, 286, 455};

// Precomputed (input-independent) tables, rebuilt every launch by prep kernel.
__device__ float g_Yre[MTOT * 196];
__device__ float g_Yim[MTOT * 196];
__device__ int   g_boff[4 * 4096];
__device__ float g_bw[4 * 4096];

// ---------------------------------------------------------------------------
// Prep kernel: fully parallel. First 9604 threads: Y tables (float math).
// Next 4096 threads: bilinear tap tables (double math, few ops each).
// ---------------------------------------------------------------------------
__global__ void prep_kernel() {
    const int gid = blockIdx.x * blockDim.x + threadIdx.x;
    const float PI_F = 3.14159265358979323846f;
    const double PI_D = 3.14159265358979323846;

    if (gid < MTOT * 196) {
        const int midx = gid / 196;
        const int col = gid - midx * 196;
        const int jb = col / JGRID;
        const int k = col - jb * JGRID;
        int l = 0;
        while ((l + 1) * (l + 1) <= midx) ++l;
        const int ms = midx - (l * l + l);       // signed m
        const int ma = ms < 0 ? -ms : ms;

        const float beta = PI_F * (2.0f * jb + 1.0f) / 28.0f;
        float x, sx;
        sincosf(beta, &sx, &x);                   // x=cos, sx=sin

        // associated Legendre P_l^ma(x) via standard recurrence
        float pmm = 1.0f;
        for (int m = 1; m <= ma; ++m) pmm = -(2.0f * m - 1.0f) * sx * pmm;
        float p = pmm;
        if (l > ma) {
            float pm1 = pmm;
            float pcur = (2.0f * ma + 1.0f) * x * pmm;
            for (int ll = ma + 2; ll <= l; ++ll) {
                float pn = ((2.0f * ll - 1.0f) * x * pcur -
                            (ll + ma - 1.0f) * pm1) / (float)(ll - ma);
                pm1 = pcur; pcur = pn;
            }
            p = pcur;
        }
        const float Nrm = sqrtf((2.0f * l + 1.0f) / (4.0f * PI_F) *
                                c_FACT[l - ma] / c_FACT[l + ma]);
        const float pr = Nrm * p;
        const float alpha = 2.0f * PI_F * (float)k / 14.0f;
        float sa, ca;
        sincosf((float)ma * alpha, &sa, &ca);
        float yre = pr * ca;
        float yim = pr * sa;
        if (ms < 0) {
            const float sgn = (ma & 1) ? -1.0f : 1.0f;
            yre = sgn * yre;
            yim = -sgn * yim;
        }
        g_Yre[gid] = yre;
        g_Yim[gid] = yim;
    } else if (gid < MTOT * 196 + 4096) {
        const int p = gid - MTOT * 196;
        const int py = p >> 6, px = p & 63;
        const double r = 0.8;
        const double yv = -r + py * (2.0 * r / 63.0);
        const double xv = -r + px * (2.0 * r / 63.0);
        double rho = sqrt(xv * xv + yv * yv);
        if (rho > 1.0) rho = 1.0;
        const double th = asin(rho);
        const double ph = atan2(yv, xv);
        const float gx = (float)(ph / PI_D);
        const float gy = (float)(2.0 * th / PI_D - 1.0);
        const float gxp = (gx + 1.0f) * 7.0f - 0.5f;
        const float gyp = (gy + 1.0f) * 7.0f - 0.5f;
        const float x0f = floorf(gxp), y0f = floorf(gyp);
        const float wx1 = gxp - x0f, wx0 = 1.0f - wx1;
        const float wy1 = gyp - y0f, wy0 = 1.0f - wy1;
        const int xi0 = (int)x0f, yi0 = (int)y0f;
        const int xs[4] = {xi0, xi0 + 1, xi0, xi0 + 1};
        const int ys[4] = {yi0, yi0, yi0 + 1, yi0 + 1};
        const float ws[4] = {wx0 * wy0, wx1 * wy0, wx0 * wy1, wx1 * wy1};
#pragma unroll
        for (int t = 0; t < 4; ++t) {
            const bool valid = (xs[t] >= 0) && (xs[t] < 14) &&
                               (ys[t] >= 0) && (ys[t] < 14);
            int xc = xs[t] < 0 ? 0 : (xs[t] > 13 ? 13 : xs[t]);
            int yc = ys[t] < 0 ? 0 : (ys[t] > 13 ? 13 : ys[t]);
            g_boff[t * 4096 + p] = yc * 14 + xc;
            g_bw[t * 4096 + p] = valid ? ws[t] : 0.0f;
        }
    }
}

// ---------------------------------------------------------------------------
// Main fused kernel: one CTA per sample, 2 CTAs/SM.
// smem layout (float index):
//  [0..79]      trig
//  [80..239]    wt (10*16)
//  [240..695]   wigner d (455)
//  [696..1283]  Sre (49*12)
//  [1284..1871] Sim (49*12)
//  [1872..4223] sig (196*12)  (aliased as staged spectrum before phase 3)
//  bytes 16896..106655: proj as half, 10 planes of 66x68 (pitch 68 halves)
// ---------------------------------------------------------------------------
#define SM_TRIG 0
#define SM_WT   80
#define SM_D    240
#define SM_SRE  696
#define SM_SIM  1284
#define SM_SIG  1872
#define SM_PROJ_F 4224          // float offset where half proj region starts
#define PROJ_PITCH_H 68         // halves per row
#define PROJ_PLANE_H (66 * 68)  // 4488 halves per channel
#define SMEM_BYTES (SM_PROJ_F * 4 + 10 * PROJ_PLANE_H * 2)  // 106656

__global__ __launch_bounds__(512, 2)
void decoder_kernel(const float* __restrict__ angles,
                    const float* __restrict__ spectrum,
                    const float* __restrict__ wt,
                    const float* __restrict__ bt,
                    float* __restrict__ out) {
    extern __shared__ float sm[];
    const int tid = threadIdx.x;
    const int n = blockIdx.x;

    float* s_trig = sm + SM_TRIG;
    float* s_wt   = sm + SM_WT;
    float* s_d    = sm + SM_D;
    float* s_Sre  = sm + SM_SRE;
    float* s_Sim  = sm + SM_SIM;
    float* s_sig  = sm + SM_SIG;
    __half* s_proj = (__half*)(sm + SM_PROJ_F);
    float* s_spec = s_sig;  // alias: staged spectrum, dead before sig written

    // ---- phase 0: trig tables + staging ----
    if (tid < 13) {
        float al = angles[3 * n + 0];
        float ga = angles[3 * n + 2];
        float kk = (float)(tid - 6);
        float s, c;
        sincosf(kk * al, &s, &c); s_trig[16 + tid] = s; s_trig[0 + tid] = c;
        sincosf(kk * ga, &s, &c); s_trig[48 + tid] = s; s_trig[32 + tid] = c;
    }
    if (tid == 16) {
        float be = angles[3 * n + 1];
        float s, c;
        sincosf(0.5f * be, &s, &c);
        s_trig[64] = c; s_trig[65] = s;
    }
    for (int i = tid; i < 160; i += 512) s_wt[i] = wt[i];
    for (int i = tid; i < 980; i += 512) s_spec[i] = spectrum[i];
    __syncthreads();

    // ---- phase 1: Wigner small-d entries (455) ----
    {
        const float cb = s_trig[64], sb = s_trig[65];
        for (int e = tid; e < 455; e += 512) {
            int l = 0;
            while (l < 6 && e >= c_OFF[l + 1]) ++l;
            int r = e - c_OFF[l];
            int n1 = 2 * l + 1;
            int i = r / n1, j = r - i * n1;
            int mp = i - l, m = j - l;
            float pref = sqrtf(c_FACT[l + mp] * c_FACT[l - mp] *
                               c_FACT[l + m] * c_FACT[l - m]);
            int kmin = m - mp > 0 ? m - mp : 0;
            int kmax = (l + m) < (l - mp) ? (l + m) : (l - mp);
            float acc = 0.f;
            for (int k = kmin; k <= kmax; ++k) {
                float cc = pref / (c_FACT[l + m - k] * c_FACT[k] *
                                   c_FACT[l - mp - k] * c_FACT[mp - m + k]);
                if ((mp - m + k) & 1) cc = -cc;
                int pc = 2 * l + m - mp - 2 * k;
                int ps = mp - m + 2 * k;
                float pcv = 1.f;
                for (int q = 0; q < pc; ++q) pcv *= cb;
                float psv = 1.f;
                for (int q = 0; q < ps; ++q) psv *= sb;
                acc += cc * pcv * psv;
            }
            s_d[e] = acc;
        }
    }
    __syncthreads();

    // ---- phase 2: rotate spectrum -> Sre/Sim (49 x 10), pitch 12 ----
    for (int idx = tid; idx < 490; idx += 512) {
        int mrow = idx / 10, c = idx - mrow * 10;
        int l = 0;
        while ((l + 1) * (l + 1) <= mrow) ++l;
        int i = mrow - l * l;
        int mp = i - l;
        float camp = s_trig[0 + mp + 6], samp = s_trig[16 + mp + 6];
        const float* dptr = s_d + c_OFF[l] + i * (2 * l + 1);
        float are = 0.f, aim = 0.f;
        for (int j = 0; j <= 2 * l; ++j) {
            int m = j - l;
            float dv = dptr[j];
            float cg = s_trig[32 + m + 6], sg = s_trig[48 + m + 6];
            float cosang = camp * cg - samp * sg;
            float sinang = samp * cg + camp * sg;
            float sre = s_spec[(l * l + j) * 20 + c * 2 + 0];
            float sim = s_spec[(l * l + j) * 20 + c * 2 + 1];
            are += dv * (cosang * sre + sinang * sim);
            aim += dv * (cosang * sim - sinang * sre);
        }
        s_Sre[mrow * 12 + c] = are;
        s_Sim[mrow * 12 + c] = aim;
    }
    __syncthreads();

    // ---- phase 3: signal[j][c] = sum_m Sre[m][c]*Yre[m][j] - Sim*Yim ----
    if (tid < 196) {
        float acc[10];
#pragma unroll
        for (int c = 0; c < 10; ++c) acc[c] = 0.f;
#pragma unroll 7
        for (int m = 0; m < 49; ++m) {
            float yre = g_Yre[m * 196 + tid];
            float yim = g_Yim[m * 196 + tid];
            float4 r0 = *(const float4*)&s_Sre[m * 12 + 0];
            float4 r1 = *(const float4*)&s_Sre[m * 12 + 4];
            float2 r2 = *(const float2*)&s_Sre[m * 12 + 8];
            float4 i0 = *(const float4*)&s_Sim[m * 12 + 0];
            float4 i1 = *(const float4*)&s_Sim[m * 12 + 4];
            float2 i2 = *(const float2*)&s_Sim[m * 12 + 8];
            acc[0] += r0.x * yre - i0.x * yim;
            acc[1] += r0.y * yre - i0.y * yim;
            acc[2] += r0.z * yre - i0.z * yim;
            acc[3] += r0.w * yre - i0.w * yim;
            acc[4] += r1.x * yre - i1.x * yim;
            acc[5] += r1.y * yre - i1.y * yim;
            acc[6] += r1.z * yre - i1.z * yim;
            acc[7] += r1.w * yre - i1.w * yim;
            acc[8] += r2.x * yre - i2.x * yim;
            acc[9] += r2.y * yre - i2.y * yim;
        }
        *(float4*)&s_sig[tid * 12 + 0] = make_float4(acc[0], acc[1], acc[2], acc[3]);
        *(float4*)&s_sig[tid * 12 + 4] = make_float4(acc[4], acc[5], acc[6], acc[7]);
        *(float2*)&s_sig[tid * 12 + 8] = make_float2(acc[8], acc[9]);
    }
    __syncthreads();

    // ---- phase 4: zero proj borders + bilinear projection (fp16 smem) ----
    {
        const __half hz = __float2half(0.0f);
        // top (row 0) and bottom (row 65) rows, full pitch
        for (int i = tid; i < 10 * PROJ_PITCH_H; i += 512) {
            int c = i / PROJ_PITCH_H, q = i - c * PROJ_PITCH_H;
            s_proj[c * PROJ_PLANE_H + q] = hz;
            s_proj[c * PROJ_PLANE_H + 65 * PROJ_PITCH_H + q] = hz;
        }
        // left (col 0) and right (col 65) columns for rows 1..64
        for (int i = tid; i < 640; i += 512) {
            int c = i / 64, rr = i - c * 64;
            s_proj[c * PROJ_PLANE_H + (rr + 1) * PROJ_PITCH_H + 0] = hz;
            s_proj[c * PROJ_PLANE_H + (rr + 1) * PROJ_PITCH_H + 65] = hz;
        }
    }
    for (int p = tid; p < 4096; p += 512) {
        int py = p >> 6, px = p & 63;
        float tv[4][10];
        float w[4];
#pragma unroll
        for (int t = 0; t < 4; ++t) {
            int off = g_boff[t * 4096 + p];
            w[t] = g_bw[t * 4096 + p];
            const float* sp = &s_sig[off * 12];
            float4 q0 = *(const float4*)(sp + 0);
            float4 q1 = *(const float4*)(sp + 4);
            float2 q2 = *(const float2*)(sp + 8);
            tv[t][0] = q0.x; tv[t][1] = q0.y; tv[t][2] = q0.z; tv[t][3] = q0.w;
            tv[t][4] = q1.x; tv[t][5] = q1.y; tv[t][6] = q1.z; tv[t][7] = q1.w;
            tv[t][8] = q2.x; tv[t][9] = q2.y;
        }
        __half* pdst = &s_proj[(py + 1) * PROJ_PITCH_H + (px + 1)];
#pragma unroll
        for (int c = 0; c < 10; ++c) {
            float v = w[0] * tv[0][c] + w[1] * tv[1][c] +
                      w[2] * tv[2][c] + w[3] * tv[3][c];
            pdst[c * PROJ_PLANE_H] = __float2half(v);
        }
    }
    __syncthreads();

    // ---- phase 5: ConvTranspose2d, 4x8 output tile per thread ----
    {
        const int b = tid & 15;      // col block (8 cols)
        const int a = tid >> 4;      // row block (4 rows)
        const float bias = bt[0];
        float acc[4][8];
#pragma unroll
        for (int dy = 0; dy < 4; ++dy)
#pragma unroll
            for (int e = 0; e < 8; ++e) acc[dy][e] = bias;

        const int rowbase = 2 * a;   // padded proj row of iy = 2a-1
        const int colbase = 4 * b;   // padded proj col of ix = 4b-1

        const int R1[4] = {1, 2, 2, 3};
        const int KH1[4] = {1, 0, 1, 0};
        const int R2[4] = {0, 1, 1, 2};
        const int KH2[4] = {3, 2, 3, 2};
        const int C1[8] = {1, 2, 2, 3, 3, 4, 4, 5};
        const int KW1[8] = {1, 0, 1, 0, 1, 0, 1, 0};
        const int C2[8] = {0, 1, 1, 2, 2, 3, 3, 4};
        const int KW2[8] = {3, 2, 3, 2, 3, 2, 3, 2};

#pragma unroll 1
        for (int c = 0; c < 10; ++c) {
            float w[16];
            const float* pw = s_wt + c * 16;
            float4 w0 = *(const float4*)(pw + 0);
            float4 w1 = *(const float4*)(pw + 4);
            float4 w2 = *(const float4*)(pw + 8);
            float4 w3 = *(const float4*)(pw + 12);
            w[0] = w0.x; w[1] = w0.y; w[2] = w0.z; w[3] = w0.w;
            w[4] = w1.x; w[5] = w1.y; w[6] = w1.z; w[7] = w1.w;
            w[8] = w2.x; w[9] = w2.y; w[10] = w2.z; w[11] = w2.w;
            w[12] = w3.x; w[13] = w3.y; w[14] = w3.z; w[15] = w3.w;

            float pv[4][6];
            const __half* pp = s_proj + c * PROJ_PLANE_H +
                               rowbase * PROJ_PITCH_H + colbase;
#pragma unroll
            for (int r = 0; r < 4; ++r) {
                uint2 u = *reinterpret_cast<const uint2*>(pp + r * PROJ_PITCH_H);
                unsigned int u2 =
                    *reinterpret_cast<const unsigned int*>(pp + r * PROJ_PITCH_H + 4);
                float2 f0 = __half22float2(*reinterpret_cast<__half2*>(&u.x));
                float2 f1 = __half22float2(*reinterpret_cast<__half2*>(&u.y));
                float2 f2 = __half22float2(*reinterpret_cast<__half2*>(&u2));
                pv[r][0] = f0.x; pv[r][1] = f0.y;
                pv[r][2] = f1.x; pv[r][3] = f1.y;
                pv[r][4] = f2.x; pv[r][5] = f2.y;
            }

#pragma unroll
            for (int dy = 0; dy < 4; ++dy) {
                const int r1 = R1[dy], r2 = R2[dy];
                const int h1 = KH1[dy] * 4, h2 = KH2[dy] * 4;
#pragma unroll
                for (int e = 0; e < 8; ++e) {
                    acc[dy][e] += pv[r1][C1[e]] * w[h1 + KW1[e]];
                    acc[dy][e] += pv[r1][C2[e]] * w[h1 + KW2[e]];
                    acc[dy][e] += pv[r2][C1[e]] * w[h2 + KW1[e]];
                    acc[dy][e] += pv[r2][C2[e]] * w[h2 + KW2[e]];
                }
            }
        }

        float* op = out + (size_t)n * 16384 + (size_t)(4 * a) * 128 + 8 * b;
#pragma unroll
        for (int dy = 0; dy < 4; ++dy) {
            *(float4*)(op + dy * 128 + 0) =
                make_float4(acc[dy][0], acc[dy][1], acc[dy][2], acc[dy][3]);
            *(float4*)(op + dy * 128 + 4) =
                make_float4(acc[dy][4], acc[dy][5], acc[dy][6], acc[dy][7]);
        }
    }
}

// ---------------------------------------------------------------------------
extern "C" void kernel_launch(void* const* d_in, const int* in_sizes, int n_in,
                              void* d_out, int out_size) {
    const float* angles   = (const float*)d_in[0];
    const float* spectrum = (const float*)d_in[1];
    const float* wt       = (const float*)d_in[2];
    const float* bt       = (const float*)d_in[3];
    float* out = (float*)d_out;
    (void)in_sizes; (void)n_in; (void)out_size;

    cudaFuncSetAttribute(decoder_kernel,
                         cudaFuncAttributeMaxDynamicSharedMemorySize,
                         SMEM_BYTES);

    prep_kernel<<<54, 256>>>();
    decoder_kernel<<<2048, 512, SMEM_BYTES>>>(angles, spectrum, wt, bt, out);
}

// round 5
// speedup vs baseline: 5.8414x; 1.1046x over previous
#include <cuda_runtime.h>
#include <cuda_fp16.h>
#include <math.h>
#include <stdint.h>

// ---------------------------------------------------------------------------
// ProjectionDecoder fused kernel.
// Pipeline per sample n (2048): Wigner-D rotate (49x10 complex) ->
// signal 10x14x14 (fp16 smem) -> bilinear proj 10x64x64 (fp16 smem) ->
// convT 4x4 s2 p1 -> 1x128x128 fp32.
// ---------------------------------------------------------------------------

#define NDEG 6
#define MTOT 49
#define JGRID 14

__constant__ float c_FACT[13] = {
    1.f, 1.f, 2.f, 6.f, 24.f, 120.f, 720.f, 5040.f, 40320.f,
    362880.f, 3628800.f, 39916800.f, 479001600.f};
__constant__ int c_OFF[8] = {0, 1, 10, 35, 84, 165, 286, 455};

// Precomputed (input-independent) tables, rebuilt every launch by prep kernel.
__device__ float g_Yre[MTOT * 196];
__device__ float g_Yim[MTOT * 196];
__device__ int4   g_toff[4096];   // 4 tap offsets, premultiplied by 12 (halves)
__device__ float4 g_tw[4096];     // 4 tap weights

// ---------------------------------------------------------------------------
// Prep kernel: fully parallel, all fp32.
// ---------------------------------------------------------------------------
__global__ void prep_kernel() {
    const int gid = blockIdx.x * blockDim.x + threadIdx.x;
    const float PI_F = 3.14159265358979323846f;

    if (gid < MTOT * 196) {
        const int midx = gid / 196;
        const int col = gid - midx * 196;
        const int jb = col / JGRID;
        const int k = col - jb * JGRID;
        int l = 0;
        while ((l + 1) * (l + 1) <= midx) ++l;
        const int ms = midx - (l * l + l);       // signed m
        const int ma = ms < 0 ? -ms : ms;

        const float beta = PI_F * (2.0f * jb + 1.0f) / 28.0f;
        float x, sx;
        sincosf(beta, &sx, &x);                   // x=cos arg? sx=sin, x=cos

        // associated Legendre P_l^ma(x)
        float pmm = 1.0f;
        for (int m = 1; m <= ma; ++m) pmm = -(2.0f * m - 1.0f) * sx * pmm;
        float p = pmm;
        if (l > ma) {
            float pm1 = pmm;
            float pcur = (2.0f * ma + 1.0f) * x * pmm;
            for (int ll = ma + 2; ll <= l; ++ll) {
                float pn = ((2.0f * ll - 1.0f) * x * pcur -
                            (ll + ma - 1.0f) * pm1) / (float)(ll - ma);
                pm1 = pcur; pcur = pn;
            }
            p = pcur;
        }
        const float Nrm = sqrtf((2.0f * l + 1.0f) / (4.0f * PI_F) *
                                c_FACT[l - ma] / c_FACT[l + ma]);
        const float pr = Nrm * p;
        const float alpha = 2.0f * PI_F * (float)k / 14.0f;
        float sa, ca;
        sincosf((float)ma * alpha, &sa, &ca);
        float yre = pr * ca;
        float yim = pr * sa;
        if (ms < 0) {
            const float sgn = (ma & 1) ? -1.0f : 1.0f;
            yre = sgn * yre;
            yim = -sgn * yim;
        }
        g_Yre[gid] = yre;
        g_Yim[gid] = yim;
    } else if (gid < MTOT * 196 + 4096) {
        const int p = gid - MTOT * 196;
        const int py = p >> 6, px = p & 63;
        const float r = 0.8f;
        const float yv = -r + py * (2.0f * r / 63.0f);
        const float xv = -r + px * (2.0f * r / 63.0f);
        float rho = sqrtf(xv * xv + yv * yv);
        if (rho > 1.0f) rho = 1.0f;
        const float th = asinf(rho);
        const float ph = atan2f(yv, xv);
        const float gx = ph / PI_F;
        const float gy = 2.0f * th / PI_F - 1.0f;
        const float gxp = (gx + 1.0f) * 7.0f - 0.5f;
        const float gyp = (gy + 1.0f) * 7.0f - 0.5f;
        const float x0f = floorf(gxp), y0f = floorf(gyp);
        const float wx1 = gxp - x0f, wx0 = 1.0f - wx1;
        const float wy1 = gyp - y0f, wy0 = 1.0f - wy1;
        const int xi0 = (int)x0f, yi0 = (int)y0f;
        const int xs[4] = {xi0, xi0 + 1, xi0, xi0 + 1};
        const int ys[4] = {yi0, yi0, yi0 + 1, yi0 + 1};
        const float ws[4] = {wx0 * wy0, wx1 * wy0, wx0 * wy1, wx1 * wy1};
        int o[4]; float w[4];
#pragma unroll
        for (int t = 0; t < 4; ++t) {
            const bool valid = (xs[t] >= 0) && (xs[t] < 14) &&
                               (ys[t] >= 0) && (ys[t] < 14);
            int xc = xs[t] < 0 ? 0 : (xs[t] > 13 ? 13 : xs[t]);
            int yc = ys[t] < 0 ? 0 : (ys[t] > 13 ? 13 : ys[t]);
            o[t] = (yc * 14 + xc) * 12;          // premultiplied: halves pitch
            w[t] = valid ? ws[t] : 0.0f;
        }
        g_toff[p] = make_int4(o[0], o[1], o[2], o[3]);
        g_tw[p] = make_float4(w[0], w[1], w[2], w[3]);
    }
}

// ---------------------------------------------------------------------------
// Main fused kernel: one CTA per sample, 2 CTAs/SM.
// smem layout (float index):
//  [0..79]      trig
//  [80..239]    wt (10*16)
//  [240..695]   wigner d (455)
//  [696..1283]  Sre (49*12)
//  [1284..1871] Sim (49*12)
//  [1872..2851] spec staging (980)
//  [2856..4031] sig as half, 196*12 halves (pitch 12 halves = 24B)
//  [4032.. )    proj as half, 10 planes of 66x68 halves
// ---------------------------------------------------------------------------
#define SM_TRIG 0
#define SM_WT   80
#define SM_D    240
#define SM_SRE  696
#define SM_SIM  1284
#define SM_SPEC 1872
#define SM_SIGH_F 2856          // float offset of half sig buffer
#define SM_PROJ_F 4032          // float offset of half proj buffer
#define PROJ_PITCH_H 68
#define PROJ_PLANE_H (66 * 68)  // 4488 halves
#define SMEM_BYTES (SM_PROJ_F * 4 + 10 * PROJ_PLANE_H * 2)  // 105888

__global__ __launch_bounds__(512, 2)
void decoder_kernel(const float* __restrict__ angles,
                    const float* __restrict__ spectrum,
                    const float* __restrict__ wt,
                    const float* __restrict__ bt,
                    float* __restrict__ out) {
    extern __shared__ float sm[];
    const int tid = threadIdx.x;
    const int n = blockIdx.x;

    float* s_trig = sm + SM_TRIG;
    float* s_wt   = sm + SM_WT;
    float* s_d    = sm + SM_D;
    float* s_Sre  = sm + SM_SRE;
    float* s_Sim  = sm + SM_SIM;
    float* s_spec = sm + SM_SPEC;
    __half* s_sigh = (__half*)(sm + SM_SIGH_F);
    __half* s_proj = (__half*)(sm + SM_PROJ_F);

    // ---- phase 0: trig tables + staging ----
    if (tid < 13) {
        float al = angles[3 * n + 0];
        float ga = angles[3 * n + 2];
        float kk = (float)(tid - 6);
        float s, c;
        sincosf(kk * al, &s, &c); s_trig[16 + tid] = s; s_trig[0 + tid] = c;
        sincosf(kk * ga, &s, &c); s_trig[48 + tid] = s; s_trig[32 + tid] = c;
    }
    if (tid == 16) {
        float be = angles[3 * n + 1];
        float s, c;
        sincosf(0.5f * be, &s, &c);
        s_trig[64] = c; s_trig[65] = s;
    }
    for (int i = tid; i < 160; i += 512) s_wt[i] = wt[i];
    for (int i = tid; i < 980; i += 512) s_spec[i] = spectrum[i];
    __syncthreads();

    // ---- phase 1: Wigner small-d entries (455) ----
    {
        const float cb = s_trig[64], sb = s_trig[65];
        for (int e = tid; e < 455; e += 512) {
            int l = 0;
            while (l < 6 && e >= c_OFF[l + 1]) ++l;
            int r = e - c_OFF[l];
            int n1 = 2 * l + 1;
            int i = r / n1, j = r - i * n1;
            int mp = i - l, m = j - l;
            float pref = sqrtf(c_FACT[l + mp] * c_FACT[l - mp] *
                               c_FACT[l + m] * c_FACT[l - m]);
            int kmin = m - mp > 0 ? m - mp : 0;
            int kmax = (l + m) < (l - mp) ? (l + m) : (l - mp);
            float acc = 0.f;
            for (int k = kmin; k <= kmax; ++k) {
                float cc = pref / (c_FACT[l + m - k] * c_FACT[k] *
                                   c_FACT[l - mp - k] * c_FACT[mp - m + k]);
                if ((mp - m + k) & 1) cc = -cc;
                int pc = 2 * l + m - mp - 2 * k;
                int ps = mp - m + 2 * k;
                float pcv = 1.f;
                for (int q = 0; q < pc; ++q) pcv *= cb;
                float psv = 1.f;
                for (int q = 0; q < ps; ++q) psv *= sb;
                acc += cc * pcv * psv;
            }
            s_d[e] = acc;
        }
    }
    __syncthreads();

    // ---- phase 2: rotate spectrum -> Sre/Sim (49 x 10), pitch 12 ----
    for (int idx = tid; idx < 490; idx += 512) {
        int mrow = idx / 10, c = idx - mrow * 10;
        int l = 0;
        while ((l + 1) * (l + 1) <= mrow) ++l;
        int i = mrow - l * l;
        int mp = i - l;
        float camp = s_trig[0 + mp + 6], samp = s_trig[16 + mp + 6];
        const float* dptr = s_d + c_OFF[l] + i * (2 * l + 1);
        float are = 0.f, aim = 0.f;
        for (int j = 0; j <= 2 * l; ++j) {
            int m = j - l;
            float dv = dptr[j];
            float cg = s_trig[32 + m + 6], sg = s_trig[48 + m + 6];
            float cosang = camp * cg - samp * sg;
            float sinang = samp * cg + camp * sg;
            float sre = s_spec[(l * l + j) * 20 + c * 2 + 0];
            float sim = s_spec[(l * l + j) * 20 + c * 2 + 1];
            are += dv * (cosang * sre + sinang * sim);
            aim += dv * (cosang * sim - sinang * sre);
        }
        s_Sre[mrow * 12 + c] = are;
        s_Sim[mrow * 12 + c] = aim;
    }
    __syncthreads();

    // ---- phase 3: signal[j][c] = sum_m Sre[m][c]*Yre[m][j] - Sim*Yim ----
    if (tid < 196) {
        float acc[10];
#pragma unroll
        for (int c = 0; c < 10; ++c) acc[c] = 0.f;
#pragma unroll 7
        for (int m = 0; m < 49; ++m) {
            float yre = g_Yre[m * 196 + tid];
            float yim = g_Yim[m * 196 + tid];
            float4 r0 = *(const float4*)&s_Sre[m * 12 + 0];
            float4 r1 = *(const float4*)&s_Sre[m * 12 + 4];
            float2 r2 = *(const float2*)&s_Sre[m * 12 + 8];
            float4 i0 = *(const float4*)&s_Sim[m * 12 + 0];
            float4 i1 = *(const float4*)&s_Sim[m * 12 + 4];
            float2 i2 = *(const float2*)&s_Sim[m * 12 + 8];
            acc[0] += r0.x * yre - i0.x * yim;
            acc[1] += r0.y * yre - i0.y * yim;
            acc[2] += r0.z * yre - i0.z * yim;
            acc[3] += r0.w * yre - i0.w * yim;
            acc[4] += r1.x * yre - i1.x * yim;
            acc[5] += r1.y * yre - i1.y * yim;
            acc[6] += r1.z * yre - i1.z * yim;
            acc[7] += r1.w * yre - i1.w * yim;
            acc[8] += r2.x * yre - i2.x * yim;
            acc[9] += r2.y * yre - i2.y * yim;
        }
        __half2* dst = (__half2*)(s_sigh + tid * 12);
        dst[0] = __floats2half2_rn(acc[0], acc[1]);
        dst[1] = __floats2half2_rn(acc[2], acc[3]);
        dst[2] = __floats2half2_rn(acc[4], acc[5]);
        dst[3] = __floats2half2_rn(acc[6], acc[7]);
        dst[4] = __floats2half2_rn(acc[8], acc[9]);
    }
    __syncthreads();

    // ---- phase 4: zero proj borders + bilinear projection (fp16 smem) ----
    {
        const __half hz = __float2half(0.0f);
        for (int i = tid; i < 10 * PROJ_PITCH_H; i += 512) {
            int c = i / PROJ_PITCH_H, q = i - c * PROJ_PITCH_H;
            s_proj[c * PROJ_PLANE_H + q] = hz;
            s_proj[c * PROJ_PLANE_H + 65 * PROJ_PITCH_H + q] = hz;
        }
        for (int i = tid; i < 640; i += 512) {
            int c = i / 64, rr = i - c * 64;
            s_proj[c * PROJ_PLANE_H + (rr + 1) * PROJ_PITCH_H + 0] = hz;
            s_proj[c * PROJ_PLANE_H + (rr + 1) * PROJ_PITCH_H + 65] = hz;
        }
    }
#pragma unroll 2
    for (int p = tid; p < 4096; p += 512) {
        const int py = p >> 6, px = p & 63;
        const int4 o4 = g_toff[p];
        const float4 w4 = g_tw[p];
        const int oa[4] = {o4.x, o4.y, o4.z, o4.w};
        const float wa[4] = {w4.x, w4.y, w4.z, w4.w};
        float a0 = 0.f, a1 = 0.f, a2 = 0.f, a3 = 0.f, a4 = 0.f;
        float b0 = 0.f, b1 = 0.f, b2 = 0.f, b3 = 0.f, b4 = 0.f;
#pragma unroll
        for (int t = 0; t < 4; ++t) {
            const __half* sp = s_sigh + oa[t];
            uint2 u01 = *(const uint2*)(sp);       // halves 0..3
            uint2 u23 = *(const uint2*)(sp + 4);   // halves 4..7
            unsigned u4 = *(const unsigned*)(sp + 8); // halves 8..9
            float2 f0 = __half22float2(*(__half2*)&u01.x);
            float2 f1 = __half22float2(*(__half2*)&u01.y);
            float2 f2 = __half22float2(*(__half2*)&u23.x);
            float2 f3 = __half22float2(*(__half2*)&u23.y);
            float2 f4 = __half22float2(*(__half2*)&u4);
            const float w = wa[t];
            a0 += w * f0.x; b0 += w * f0.y;
            a1 += w * f1.x; b1 += w * f1.y;
            a2 += w * f2.x; b2 += w * f2.y;
            a3 += w * f3.x; b3 += w * f3.y;
            a4 += w * f4.x; b4 += w * f4.y;
        }
        __half* pdst = &s_proj[(py + 1) * PROJ_PITCH_H + (px + 1)];
        pdst[0 * PROJ_PLANE_H] = __float2half(a0);
        pdst[1 * PROJ_PLANE_H] = __float2half(b0);
        pdst[2 * PROJ_PLANE_H] = __float2half(a1);
        pdst[3 * PROJ_PLANE_H] = __float2half(b1);
        pdst[4 * PROJ_PLANE_H] = __float2half(a2);
        pdst[5 * PROJ_PLANE_H] = __float2half(b2);
        pdst[6 * PROJ_PLANE_H] = __float2half(a3);
        pdst[7 * PROJ_PLANE_H] = __float2half(b3);
        pdst[8 * PROJ_PLANE_H] = __float2half(a4);
        pdst[9 * PROJ_PLANE_H] = __float2half(b4);
    }
    __syncthreads();

    // ---- phase 5: ConvTranspose2d, 4x8 output tile per thread ----
    {
        const int b = tid & 15;      // col block (8 cols)
        const int a = tid >> 4;      // row block (4 rows)
        const float bias = bt[0];
        float acc[4][8];
#pragma unroll
        for (int dy = 0; dy < 4; ++dy)
#pragma unroll
            for (int e = 0; e < 8; ++e) acc[dy][e] = bias;

        const int rowbase = 2 * a;   // padded proj row of iy = 2a-1
        const int colbase = 4 * b;   // padded proj col of ix = 4b-1

        const int R1[4] = {1, 2, 2, 3};
        const int KH1[4] = {1, 0, 1, 0};
        const int R2[4] = {0, 1, 1, 2};
        const int KH2[4] = {3, 2, 3, 2};
        const int C1[8] = {1, 2, 2, 3, 3, 4, 4, 5};
        const int KW1[8] = {1, 0, 1, 0, 1, 0, 1, 0};
        const int C2[8] = {0, 1, 1, 2, 2, 3, 3, 4};
        const int KW2[8] = {3, 2, 3, 2, 3, 2, 3, 2};

#pragma unroll 1
        for (int c = 0; c < 10; ++c) {
            float w[16];
            const float* pw = s_wt + c * 16;
            float4 w0 = *(const float4*)(pw + 0);
            float4 w1 = *(const float4*)(pw + 4);
            float4 w2 = *(const float4*)(pw + 8);
            float4 w3 = *(const float4*)(pw + 12);
            w[0] = w0.x; w[1] = w0.y; w[2] = w0.z; w[3] = w0.w;
            w[4] = w1.x; w[5] = w1.y; w[6] = w1.z; w[7] = w1.w;
            w[8] = w2.x; w[9] = w2.y; w[10] = w2.z; w[11] = w2.w;
            w[12] = w3.x; w[13] = w3.y; w[14] = w3.z; w[15] = w3.w;

            float pv[4][6];
            const __half* pp = s_proj + c * PROJ_PLANE_H +
                               rowbase * PROJ_PITCH_H + colbase;
#pragma unroll
            for (int r = 0; r < 4; ++r) {
                uint2 u = *reinterpret_cast<const uint2*>(pp + r * PROJ_PITCH_H);
                unsigned int u2 =
                    *reinterpret_cast<const unsigned int*>(pp + r * PROJ_PITCH_H + 4);
                float2 f0 = __half22float2(*reinterpret_cast<__half2*>(&u.x));
                float2 f1 = __half22float2(*reinterpret_cast<__half2*>(&u.y));
                float2 f2 = __half22float2(*reinterpret_cast<__half2*>(&u2));
                pv[r][0] = f0.x; pv[r][1] = f0.y;
                pv[r][2] = f1.x; pv[r][3] = f1.y;
                pv[r][4] = f2.x; pv[r][5] = f2.y;
            }

#pragma unroll
            for (int dy = 0; dy < 4; ++dy) {
                const int r1 = R1[dy], r2 = R2[dy];
                const int h1 = KH1[dy] * 4, h2 = KH2[dy] * 4;
#pragma unroll
                for (int e = 0; e < 8; ++e) {
                    acc[dy][e] += pv[r1][C1[e]] * w[h1 + KW1[e]];
                    acc[dy][e] += pv[r1][C2[e]] * w[h1 + KW2[e]];
                    acc[dy][e] += pv[r2][C1[e]] * w[h2 + KW1[e]];
                    acc[dy][e] += pv[r2][C2[e]] * w[h2 + KW2[e]];
                }
            }
        }

        float* op = out + (size_t)n * 16384 + (size_t)(4 * a) * 128 + 8 * b;
#pragma unroll
        for (int dy = 0; dy < 4; ++dy) {
            *(float4*)(op + dy * 128 + 0) =
                make_float4(acc[dy][0], acc[dy][1], acc[dy][2], acc[dy][3]);
            *(float4*)(op + dy * 128 + 4) =
                make_float4(acc[dy][4], acc[dy][5], acc[dy][6], acc[dy][7]);
        }
    }
}

// ---------------------------------------------------------------------------
extern "C" void kernel_launch(void* const* d_in, const int* in_sizes, int n_in,
                              void* d_out, int out_size) {
    const float* angles   = (const float*)d_in[0];
    const float* spectrum = (const float*)d_in[1];
    const float* wt       = (const float*)d_in[2];
    const float* bt       = (const float*)d_in[3];
    float* out = (float*)d_out;
    (void)in_sizes; (void)n_in; (void)out_size;

    cudaFuncSetAttribute(decoder_kernel,
                         cudaFuncAttributeMaxDynamicSharedMemorySize,
                         SMEM_BYTES);

    prep_kernel<<<54, 256>>>();
    decoder_kernel<<<2048, 512, SMEM_BYTES>>>(angles, spectrum, wt, bt, out);
}